// round 2
// baseline (speedup 1.0000x reference)
#include <cuda_runtime.h>

// ---------------------------------------------------------------------------
// ScalarDotProductCriticNetworkV8 — fused per-batch kernel.
//
// Shapes: B=512, N=16, A=16, OBS=112, D=128, H=64, F_IN=128.
//
// Algebraic restructuring:
//   avoff[b,i,:] = tanh(Wv @ [states;actions][b,i] + bv)     (j-independent!)
//   avdiag[b,i,:] = tanh(Wv @ [states;policies][b,i] + bv)
//   AW1  = avoff  @ W1.T   [16,64] per batch
//   AdW1 = avdiag @ W1.T
//   nf@W1.T [a,j,h] = ( (w@AW1)[a,h] + (AdW1-AW1)[j,h] * w[a,j] ) / N
//   value[a,j] = sum_h lrelu(.) * W2[h]
//
// Inner GEMM loops use packed fma.rn.f32x2 (2x fp32 FMA throughput on
// Blackwell) pairing adjacent rows; activations stored transposed in smem
// ([feature][row], row-stride 20) so row pairs are one LDS.128.
// ---------------------------------------------------------------------------

#define ULL unsigned long long

#define PACK2(d, lo, hi) asm("mov.b64 %0, {%1, %2};" : "=l"(d) : "f"(lo), "f"(hi))
#define UNPACK2(lo, hi, v) asm("mov.b64 {%0, %1}, %2;" : "=f"(lo), "=f"(hi) : "l"(v))
#define FMA2(acc, a, b) asm("fma.rn.f32x2 %0, %1, %2, %0;" : "+l"(acc) : "l"(a), "l"(b))

// Pre-transposed weights (scratch; filled by prep kernel each launch).
__device__ float g_WkT[112 * 128];   // [kk][c]
__device__ float g_WqT[112 * 128];   // [kk][c]
__device__ float g_WvT[128 * 128];   // [f][c]
__device__ float g_W1T[128 * 64];    // [d][h]

__global__ void prep_weights(const float* __restrict__ Wk, const float* __restrict__ Wq,
                             const float* __restrict__ Wv, const float* __restrict__ W1) {
    int t = blockIdx.x * blockDim.x + threadIdx.x;
    int stride = gridDim.x * blockDim.x;
    for (int i = t; i < 112 * 128; i += stride) {
        int kk = i >> 7, c = i & 127;
        g_WkT[i] = Wk[c * 112 + kk];
        g_WqT[i] = Wq[c * 112 + kk];
    }
    for (int i = t; i < 128 * 128; i += stride) {
        int f = i >> 7, c = i & 127;
        g_WvT[i] = Wv[c * 128 + f];
    }
    for (int i = t; i < 128 * 64; i += stride) {
        int d = i >> 6, h = i & 63;
        g_W1T[i] = W1[h * 128 + d];
    }
}

// Shared memory layout (floats):
//  stT   [112][20]  states transposed ([obs_feature][row]), rows 0..15 valid
//  actT  [16][20]   actions transposed  ([act_feature][row])
//  polT  [16][20]   policies transposed
//  k_s   [16][128]
//  q_s   [16][129]  (padded; pre-scaled by 1/sqrt(D))
//  avoT  [128][20]  avoff transposed  ([d][row])
//  avdT  [128][20]  avdiag transposed
//  aw1   [16][65]
//  adw1  [16][65]
//  sw1   [16][64]
//  sc    [16][17]
//  wt    [16][17]
//  w2s   [64]
#define OFF_STT   0
#define OFF_ACTT  2240
#define OFF_POLT  2560
#define OFF_K     2880
#define OFF_Q     4928
#define OFF_AVO   6992
#define OFF_AVD   9552
#define OFF_AW1   12112
#define OFF_ADW1  13152
#define OFF_SW1   14192
#define OFF_SC    15216
#define OFF_WT    15488
#define OFF_W2    15760
#define SMEM_FLOATS 15824
#define SMEM_BYTES  (SMEM_FLOATS * 4)

__global__ void __launch_bounds__(256, 3)
critic_kernel(const float* __restrict__ states,
              const float* __restrict__ policies,
              const float* __restrict__ actions,
              const float* __restrict__ bk,
              const float* __restrict__ bq,
              const float* __restrict__ bv,
              const float* __restrict__ W2,
              float* __restrict__ out,
              int out_size) {
    extern __shared__ float sm[];
    float* stT  = sm + OFF_STT;
    float* actT = sm + OFF_ACTT;
    float* polT = sm + OFF_POLT;
    float* k_s  = sm + OFF_K;
    float* q_s  = sm + OFF_Q;
    float* avoT = sm + OFF_AVO;
    float* avdT = sm + OFF_AVD;
    float* aw1  = sm + OFF_AW1;
    float* adw1 = sm + OFF_ADW1;
    float* sw1  = sm + OFF_SW1;
    float* sc   = sm + OFF_SC;
    float* wt   = sm + OFF_WT;
    float* w2s  = sm + OFF_W2;

    const int t = threadIdx.x;
    const int b = blockIdx.x;

    // ---- load inputs (transposed into smem) ----
    {
        const float* stb = states + b * (16 * 112);
        for (int idx = t; idx < 16 * 112; idx += 256) {
            int r = idx / 112, kk = idx - r * 112;
            stT[kk * 20 + r] = stb[idx];
        }
        int r = t >> 4, jj = t & 15;
        actT[jj * 20 + r] = actions[b * 256 + t];
        polT[jj * 20 + r] = policies[b * 256 + t];
        if (t < 64) w2s[t] = W2[t];
    }
    __syncthreads();

    // ---- phase 1: k = states@Wk.T + bk ; q = (states@Wq.T + bq) / sqrt(D) ----
    {
        const int which = t >> 7, c = t & 127;
        const float* WT = which ? g_WqT : g_WkT;
        const float bias = which ? bq[c] : bk[c];
        ULL acc[8];
#pragma unroll
        for (int rp = 0; rp < 8; rp++) PACK2(acc[rp], bias, bias);
#pragma unroll 4
        for (int kk = 0; kk < 112; kk++) {
            float w = WT[kk * 128 + c];
            ULL w2; PACK2(w2, w, w);
            const ulonglong2* sp = reinterpret_cast<const ulonglong2*>(stT + kk * 20);
            ulonglong2 sA = sp[0], sB = sp[1];
            FMA2(acc[0], w2, sA.x); FMA2(acc[1], w2, sA.y);
            FMA2(acc[2], w2, sB.x); FMA2(acc[3], w2, sB.y);
            ulonglong2 sC = sp[2], sD = sp[3];
            FMA2(acc[4], w2, sC.x); FMA2(acc[5], w2, sC.y);
            FMA2(acc[6], w2, sD.x); FMA2(acc[7], w2, sD.y);
        }
        if (which == 0) {
#pragma unroll
            for (int rp = 0; rp < 8; rp++) {
                float lo, hi; UNPACK2(lo, hi, acc[rp]);
                k_s[(2 * rp) * 128 + c] = lo;
                k_s[(2 * rp + 1) * 128 + c] = hi;
            }
        } else {
            const float s = 0.08838834764831845f;  // 1/sqrt(128)
#pragma unroll
            for (int rp = 0; rp < 8; rp++) {
                float lo, hi; UNPACK2(lo, hi, acc[rp]);
                q_s[(2 * rp) * 129 + c] = lo * s;
                q_s[(2 * rp + 1) * 129 + c] = hi * s;
            }
        }
    }
    __syncthreads();

    // ---- phase 2: avoff = tanh([st;act]@Wv.T+bv), avdiag = tanh([st;pol]@Wv.T+bv) ----
    {
        const int which = t >> 7, c = t & 127;
        const float bias = bv[c];
        ULL acc[8];
#pragma unroll
        for (int rp = 0; rp < 8; rp++) PACK2(acc[rp], bias, bias);
#pragma unroll 4
        for (int f = 0; f < 112; f++) {
            float w = g_WvT[f * 128 + c];
            ULL w2; PACK2(w2, w, w);
            const ulonglong2* sp = reinterpret_cast<const ulonglong2*>(stT + f * 20);
            ulonglong2 sA = sp[0], sB = sp[1];
            FMA2(acc[0], w2, sA.x); FMA2(acc[1], w2, sA.y);
            FMA2(acc[2], w2, sB.x); FMA2(acc[3], w2, sB.y);
            ulonglong2 sC = sp[2], sD = sp[3];
            FMA2(acc[4], w2, sC.x); FMA2(acc[5], w2, sC.y);
            FMA2(acc[6], w2, sD.x); FMA2(acc[7], w2, sD.y);
        }
        const float* tailT = which ? polT : actT;
#pragma unroll 4
        for (int f = 0; f < 16; f++) {
            float w = g_WvT[(112 + f) * 128 + c];
            ULL w2; PACK2(w2, w, w);
            const ulonglong2* sp = reinterpret_cast<const ulonglong2*>(tailT + f * 20);
            ulonglong2 sA = sp[0], sB = sp[1];
            FMA2(acc[0], w2, sA.x); FMA2(acc[1], w2, sA.y);
            FMA2(acc[2], w2, sB.x); FMA2(acc[3], w2, sB.y);
            ulonglong2 sC = sp[2], sD = sp[3];
            FMA2(acc[4], w2, sC.x); FMA2(acc[5], w2, sC.y);
            FMA2(acc[6], w2, sD.x); FMA2(acc[7], w2, sD.y);
        }
        float v[16];
#pragma unroll
        for (int rp = 0; rp < 8; rp++) {
            float lo, hi; UNPACK2(lo, hi, acc[rp]);
            v[2 * rp] = tanhf(lo);
            v[2 * rp + 1] = tanhf(hi);
        }
        float* dst = which ? avdT : avoT;
        *reinterpret_cast<float4*>(dst + c * 20 + 0)  = make_float4(v[0], v[1], v[2], v[3]);
        *reinterpret_cast<float4*>(dst + c * 20 + 4)  = make_float4(v[4], v[5], v[6], v[7]);
        *reinterpret_cast<float4*>(dst + c * 20 + 8)  = make_float4(v[8], v[9], v[10], v[11]);
        *reinterpret_cast<float4*>(dst + c * 20 + 12) = make_float4(v[12], v[13], v[14], v[15]);
    }
    __syncthreads();

    // ---- phase 3: scores[j,i] = q[i]·k[j]  (q pre-scaled), softmax over i ----
    {
        int j = t >> 4, i = t & 15;
        float s = 0.f;
#pragma unroll 8
        for (int d = 0; d < 128; d++)
            s = fmaf(q_s[i * 129 + d], k_s[j * 128 + d], s);
        sc[j * 17 + i] = s;
    }
    __syncthreads();
    if (t < 16) {
        int j = t;
        float m = -1e30f;
#pragma unroll
        for (int i = 0; i < 16; i++) m = fmaxf(m, sc[j * 17 + i]);
        float sum = 0.f;
#pragma unroll
        for (int i = 0; i < 16; i++) {
            float e = expf(sc[j * 17 + i] - m);
            sum += e;
            wt[j * 17 + i] = e;
        }
        float inv = 1.f / sum;
#pragma unroll
        for (int i = 0; i < 16; i++) wt[j * 17 + i] *= inv;
    }
    __syncthreads();

    // ---- phase 4: AW1 = avoff@W1.T, AdW1 = avdiag@W1.T  ([16][64] each) ----
    {
        int h = t & 63, g = t >> 6;
        int m = g & 1, r0 = (g >> 1) * 8;
        const float* srcT = m ? avdT : avoT;
        float* dst = m ? adw1 : aw1;
        ULL acc[4] = {0ull, 0ull, 0ull, 0ull};
#pragma unroll 4
        for (int d = 0; d < 128; d++) {
            float w = g_W1T[d * 64 + h];
            ULL w2; PACK2(w2, w, w);
            const ulonglong2* sp = reinterpret_cast<const ulonglong2*>(srcT + d * 20 + r0);
            ulonglong2 sA = sp[0], sB = sp[1];
            FMA2(acc[0], w2, sA.x); FMA2(acc[1], w2, sA.y);
            FMA2(acc[2], w2, sB.x); FMA2(acc[3], w2, sB.y);
        }
#pragma unroll
        for (int rp = 0; rp < 4; rp++) {
            float lo, hi; UNPACK2(lo, hi, acc[rp]);
            dst[(r0 + 2 * rp) * 65 + h] = lo;
            dst[(r0 + 2 * rp + 1) * 65 + h] = hi;
        }
    }
    __syncthreads();

    // ---- phase 5a: SW1[a,h] = sum_i wt[a,i] * AW1[i,h] ----
    {
        int h = t & 63, g = t >> 6, a0 = g * 4;
        float acc[4] = {0.f, 0.f, 0.f, 0.f};
#pragma unroll
        for (int i = 0; i < 16; i++) {
            float aw_ = aw1[i * 65 + h];
#pragma unroll
            for (int aa = 0; aa < 4; aa++)
                acc[aa] = fmaf(wt[(a0 + aa) * 17 + i], aw_, acc[aa]);
        }
#pragma unroll
        for (int aa = 0; aa < 4; aa++) sw1[(a0 + aa) * 64 + h] = acc[aa];
    }
    __syncthreads();

    // ---- phase 5b: value[a,j] = sum_h lrelu((SW1[a,h]+(AdW1-AW1)[j,h]*w[a,j])/16) * W2[h] ----
    {
        int a = t >> 4, j = t & 15;
        float waj = wt[a * 17 + j];
        float acc = 0.f;
#pragma unroll 8
        for (int h = 0; h < 64; h++) {
            float dd = adw1[j * 65 + h] - aw1[j * 65 + h];
            float nf = (sw1[a * 64 + h] + dd * waj) * 0.0625f;
            float v = nf > 0.f ? nf : 0.01f * nf;
            acc = fmaf(v, w2s[h], acc);
        }
        out[b * 256 + t] = acc;                       // value[b, a, j, 0]
        if (out_size >= 262144)
            out[131072 + b * 256 + t] = wt[(t >> 4) * 17 + (t & 15)];  // weight[b, j, i]
    }
}

extern "C" void kernel_launch(void* const* d_in, const int* in_sizes, int n_in,
                              void* d_out, int out_size) {
    const float* states   = (const float*)d_in[0];
    const float* policies = (const float*)d_in[1];
    const float* actions  = (const float*)d_in[2];
    const float* Wk       = (const float*)d_in[3];
    const float* bk       = (const float*)d_in[4];
    const float* Wq       = (const float*)d_in[5];
    const float* bq       = (const float*)d_in[6];
    const float* Wv       = (const float*)d_in[7];
    const float* bv       = (const float*)d_in[8];
    const float* W1       = (const float*)d_in[9];
    const float* W2       = (const float*)d_in[10];
    float* out = (float*)d_out;

    cudaFuncSetAttribute(critic_kernel, cudaFuncAttributeMaxDynamicSharedMemorySize, SMEM_BYTES);

    prep_weights<<<48, 256>>>(Wk, Wq, Wv, W1);
    critic_kernel<<<512, 256, SMEM_BYTES>>>(states, policies, actions,
                                            bk, bq, bv, W2, out, out_size);
}

// round 3
// speedup vs baseline: 1.0290x; 1.0290x over previous
#include <cuda_runtime.h>

// ---------------------------------------------------------------------------
// ScalarDotProductCriticNetworkV8 — fused per-batch kernel (R3).
//
// Shapes: B=512, N=16, A=16, OBS=112, D=128, H=64, F_IN=128.
//
// R3 changes vs R2 (73.8us, occ3, 2 waves):
//  * smem 61.8KB -> 49.7KB (alias k/q region with aw1/adw1/sw1; drop sc)
//  * __launch_bounds__(256,4): occ 4 -> 592 CTA capacity -> single wave
//  * tanh.approx.f32 instead of tanhf
//  * softmax via __shfl_xor across all 256 threads (no 16-thread serial tail)
// ---------------------------------------------------------------------------

#define ULL unsigned long long

#define PACK2(d, lo, hi) asm("mov.b64 %0, {%1, %2};" : "=l"(d) : "f"(lo), "f"(hi))
#define UNPACK2(lo, hi, v) asm("mov.b64 {%0, %1}, %2;" : "=f"(lo), "=f"(hi) : "l"(v))
#define FMA2(acc, a, b) asm("fma.rn.f32x2 %0, %1, %2, %0;" : "+l"(acc) : "l"(a), "l"(b))
#define TANHA(y, x) asm("tanh.approx.f32 %0, %1;" : "=f"(y) : "f"(x))

// Pre-transposed weights (scratch; filled by prep kernel each launch).
__device__ float g_WkT[112 * 128];   // [kk][c]
__device__ float g_WqT[112 * 128];   // [kk][c]
__device__ float g_WvT[128 * 128];   // [f][c]
__device__ float g_W1T[128 * 64];    // [d][h]

__global__ void prep_weights(const float* __restrict__ Wk, const float* __restrict__ Wq,
                             const float* __restrict__ Wv, const float* __restrict__ W1) {
    int t = blockIdx.x * blockDim.x + threadIdx.x;
    int stride = gridDim.x * blockDim.x;
    for (int i = t; i < 112 * 128; i += stride) {
        int kk = i >> 7, c = i & 127;
        g_WkT[i] = Wk[c * 112 + kk];
        g_WqT[i] = Wq[c * 112 + kk];
    }
    for (int i = t; i < 128 * 128; i += stride) {
        int f = i >> 7, c = i & 127;
        g_WvT[i] = Wv[c * 128 + f];
    }
    for (int i = t; i < 128 * 64; i += stride) {
        int d = i >> 6, h = i & 63;
        g_W1T[i] = W1[h * 128 + d];
    }
}

// Shared memory layout (floats), with region X aliased across phases:
//  stT   [112][20]  @0      states transposed, rows 0..15 valid
//  actT  [16][20]   @2240
//  polT  [16][20]   @2560
//  X     [4112]     @2880 :
//     phases 1-3:  k_s[16][128] @2880,  q_s[16][129] @4928 (pre-scaled)
//     phases 4-5:  aw1[16][65] @2880, adw1[16][65] @3920, sw1[16][64] @4960
//  avoT  [128][20]  @6992
//  avdT  [128][20]  @9552
//  wt    [16][17]   @12112
//  w2s   [64]       @12384
#define OFF_STT   0
#define OFF_ACTT  2240
#define OFF_POLT  2560
#define OFF_K     2880
#define OFF_Q     4928
#define OFF_AW1   2880
#define OFF_ADW1  3920
#define OFF_SW1   4960
#define OFF_AVO   6992
#define OFF_AVD   9552
#define OFF_WT    12112
#define OFF_W2    12384
#define SMEM_FLOATS 12448
#define SMEM_BYTES  (SMEM_FLOATS * 4)

__global__ void __launch_bounds__(256, 4)
critic_kernel(const float* __restrict__ states,
              const float* __restrict__ policies,
              const float* __restrict__ actions,
              const float* __restrict__ bk,
              const float* __restrict__ bq,
              const float* __restrict__ bv,
              const float* __restrict__ W2,
              float* __restrict__ out,
              int out_size) {
    extern __shared__ float sm[];
    float* stT  = sm + OFF_STT;
    float* actT = sm + OFF_ACTT;
    float* polT = sm + OFF_POLT;
    float* k_s  = sm + OFF_K;
    float* q_s  = sm + OFF_Q;
    float* aw1  = sm + OFF_AW1;
    float* adw1 = sm + OFF_ADW1;
    float* sw1  = sm + OFF_SW1;
    float* avoT = sm + OFF_AVO;
    float* avdT = sm + OFF_AVD;
    float* wt   = sm + OFF_WT;
    float* w2s  = sm + OFF_W2;

    const int t = threadIdx.x;
    const int b = blockIdx.x;

    // ---- load inputs (transposed into smem) ----
    {
        const float* stb = states + b * (16 * 112);
        for (int idx = t; idx < 16 * 112; idx += 256) {
            int r = idx / 112, kk = idx - r * 112;
            stT[kk * 20 + r] = stb[idx];
        }
        int r = t >> 4, jj = t & 15;
        actT[jj * 20 + r] = actions[b * 256 + t];
        polT[jj * 20 + r] = policies[b * 256 + t];
        if (t < 64) w2s[t] = W2[t];
    }
    __syncthreads();

    // ---- phase 1: k = states@Wk.T + bk ; q = (states@Wq.T + bq) / sqrt(D) ----
    {
        const int which = t >> 7, c = t & 127;
        const float* WT = which ? g_WqT : g_WkT;
        const float bias = which ? bq[c] : bk[c];
        ULL acc[8];
#pragma unroll
        for (int rp = 0; rp < 8; rp++) PACK2(acc[rp], bias, bias);
#pragma unroll 2
        for (int kk = 0; kk < 112; kk++) {
            float w = WT[kk * 128 + c];
            ULL w2; PACK2(w2, w, w);
            const ulonglong2* sp = reinterpret_cast<const ulonglong2*>(stT + kk * 20);
            ulonglong2 sA = sp[0], sB = sp[1];
            FMA2(acc[0], w2, sA.x); FMA2(acc[1], w2, sA.y);
            FMA2(acc[2], w2, sB.x); FMA2(acc[3], w2, sB.y);
            ulonglong2 sC = sp[2], sD = sp[3];
            FMA2(acc[4], w2, sC.x); FMA2(acc[5], w2, sC.y);
            FMA2(acc[6], w2, sD.x); FMA2(acc[7], w2, sD.y);
        }
        if (which == 0) {
#pragma unroll
            for (int rp = 0; rp < 8; rp++) {
                float lo, hi; UNPACK2(lo, hi, acc[rp]);
                k_s[(2 * rp) * 128 + c] = lo;
                k_s[(2 * rp + 1) * 128 + c] = hi;
            }
        } else {
            const float s = 0.08838834764831845f;  // 1/sqrt(128)
#pragma unroll
            for (int rp = 0; rp < 8; rp++) {
                float lo, hi; UNPACK2(lo, hi, acc[rp]);
                q_s[(2 * rp) * 129 + c] = lo * s;
                q_s[(2 * rp + 1) * 129 + c] = hi * s;
            }
        }
    }
    __syncthreads();

    // ---- phase 2: avoff = tanh([st;act]@Wv.T+bv), avdiag = tanh([st;pol]@Wv.T+bv) ----
    {
        const int which = t >> 7, c = t & 127;
        const float bias = bv[c];
        ULL acc[8];
#pragma unroll
        for (int rp = 0; rp < 8; rp++) PACK2(acc[rp], bias, bias);
#pragma unroll 2
        for (int f = 0; f < 112; f++) {
            float w = g_WvT[f * 128 + c];
            ULL w2; PACK2(w2, w, w);
            const ulonglong2* sp = reinterpret_cast<const ulonglong2*>(stT + f * 20);
            ulonglong2 sA = sp[0], sB = sp[1];
            FMA2(acc[0], w2, sA.x); FMA2(acc[1], w2, sA.y);
            FMA2(acc[2], w2, sB.x); FMA2(acc[3], w2, sB.y);
            ulonglong2 sC = sp[2], sD = sp[3];
            FMA2(acc[4], w2, sC.x); FMA2(acc[5], w2, sC.y);
            FMA2(acc[6], w2, sD.x); FMA2(acc[7], w2, sD.y);
        }
        const float* tailT = which ? polT : actT;
#pragma unroll 2
        for (int f = 0; f < 16; f++) {
            float w = g_WvT[(112 + f) * 128 + c];
            ULL w2; PACK2(w2, w, w);
            const ulonglong2* sp = reinterpret_cast<const ulonglong2*>(tailT + f * 20);
            ulonglong2 sA = sp[0], sB = sp[1];
            FMA2(acc[0], w2, sA.x); FMA2(acc[1], w2, sA.y);
            FMA2(acc[2], w2, sB.x); FMA2(acc[3], w2, sB.y);
            ulonglong2 sC = sp[2], sD = sp[3];
            FMA2(acc[4], w2, sC.x); FMA2(acc[5], w2, sC.y);
            FMA2(acc[6], w2, sD.x); FMA2(acc[7], w2, sD.y);
        }
        float v[16];
#pragma unroll
        for (int rp = 0; rp < 8; rp++) {
            float lo, hi; UNPACK2(lo, hi, acc[rp]);
            TANHA(v[2 * rp], lo);
            TANHA(v[2 * rp + 1], hi);
        }
        float* dst = which ? avdT : avoT;
        *reinterpret_cast<float4*>(dst + c * 20 + 0)  = make_float4(v[0], v[1], v[2], v[3]);
        *reinterpret_cast<float4*>(dst + c * 20 + 4)  = make_float4(v[4], v[5], v[6], v[7]);
        *reinterpret_cast<float4*>(dst + c * 20 + 8)  = make_float4(v[8], v[9], v[10], v[11]);
        *reinterpret_cast<float4*>(dst + c * 20 + 12) = make_float4(v[12], v[13], v[14], v[15]);
    }
    __syncthreads();

    // ---- phase 3: scores[j,i] = q[i]·k[j] (q pre-scaled); softmax over i via shfl ----
    {
        int j = t >> 4, i = t & 15;
        const float* qp = q_s + i * 129;
        const float* kp = k_s + j * 128;
        float s0 = 0.f, s1 = 0.f, s2 = 0.f, s3 = 0.f;
#pragma unroll 8
        for (int d = 0; d < 128; d += 4) {
            s0 = fmaf(qp[d + 0], kp[d + 0], s0);
            s1 = fmaf(qp[d + 1], kp[d + 1], s1);
            s2 = fmaf(qp[d + 2], kp[d + 2], s2);
            s3 = fmaf(qp[d + 3], kp[d + 3], s3);
        }
        float s = (s0 + s1) + (s2 + s3);
        // max over the 16 lanes sharing j (xor offsets < 16 stay in-group)
        float m = s;
#pragma unroll
        for (int o = 8; o; o >>= 1) m = fmaxf(m, __shfl_xor_sync(0xffffffffu, m, o));
        float e = __expf(s - m);
        float sum = e;
#pragma unroll
        for (int o = 8; o; o >>= 1) sum += __shfl_xor_sync(0xffffffffu, sum, o);
        wt[j * 17 + i] = e / sum;
    }
    __syncthreads();

    // ---- phase 4: AW1 = avoff@W1.T, AdW1 = avdiag@W1.T  ([16][64] each) ----
    // (aw1/adw1 alias the dead k_s/q_s region; barrier above protects it)
    {
        int h = t & 63, g = t >> 6;
        int m = g & 1, r0 = (g >> 1) * 8;
        const float* srcT = m ? avdT : avoT;
        float* dst = m ? adw1 : aw1;
        ULL acc[4] = {0ull, 0ull, 0ull, 0ull};
#pragma unroll 4
        for (int d = 0; d < 128; d++) {
            float w = g_W1T[d * 64 + h];
            ULL w2; PACK2(w2, w, w);
            const ulonglong2* sp = reinterpret_cast<const ulonglong2*>(srcT + d * 20 + r0);
            ulonglong2 sA = sp[0], sB = sp[1];
            FMA2(acc[0], w2, sA.x); FMA2(acc[1], w2, sA.y);
            FMA2(acc[2], w2, sB.x); FMA2(acc[3], w2, sB.y);
        }
#pragma unroll
        for (int rp = 0; rp < 4; rp++) {
            float lo, hi; UNPACK2(lo, hi, acc[rp]);
            dst[(r0 + 2 * rp) * 65 + h] = lo;
            dst[(r0 + 2 * rp + 1) * 65 + h] = hi;
        }
    }
    __syncthreads();

    // ---- phase 5a: SW1[a,h] = sum_i wt[a,i] * AW1[i,h] ----
    {
        int h = t & 63, g = t >> 6, a0 = g * 4;
        float acc[4] = {0.f, 0.f, 0.f, 0.f};
#pragma unroll
        for (int i = 0; i < 16; i++) {
            float aw_ = aw1[i * 65 + h];
#pragma unroll
            for (int aa = 0; aa < 4; aa++)
                acc[aa] = fmaf(wt[(a0 + aa) * 17 + i], aw_, acc[aa]);
        }
#pragma unroll
        for (int aa = 0; aa < 4; aa++) sw1[(a0 + aa) * 64 + h] = acc[aa];
    }
    __syncthreads();

    // ---- phase 5b: value[a,j] = sum_h lrelu((SW1[a,h]+(AdW1-AW1)[j,h]*w[a,j])/16) * W2[h] ----
    {
        int a = t >> 4, j = t & 15;
        float waj = wt[a * 17 + j];
        float acc = 0.f;
#pragma unroll 8
        for (int h = 0; h < 64; h++) {
            float dd = adw1[j * 65 + h] - aw1[j * 65 + h];
            float nf = (sw1[a * 64 + h] + dd * waj) * 0.0625f;
            float v = nf > 0.f ? nf : 0.01f * nf;
            acc = fmaf(v, w2s[h], acc);
        }
        out[b * 256 + t] = acc;                       // value[b, a, j, 0]
        if (out_size >= 262144)
            out[131072 + b * 256 + t] = wt[(t >> 4) * 17 + (t & 15)];  // weight[b, j, i]
    }
}

extern "C" void kernel_launch(void* const* d_in, const int* in_sizes, int n_in,
                              void* d_out, int out_size) {
    const float* states   = (const float*)d_in[0];
    const float* policies = (const float*)d_in[1];
    const float* actions  = (const float*)d_in[2];
    const float* Wk       = (const float*)d_in[3];
    const float* bk       = (const float*)d_in[4];
    const float* Wq       = (const float*)d_in[5];
    const float* bq       = (const float*)d_in[6];
    const float* Wv       = (const float*)d_in[7];
    const float* bv       = (const float*)d_in[8];
    const float* W1       = (const float*)d_in[9];
    const float* W2       = (const float*)d_in[10];
    float* out = (float*)d_out;

    cudaFuncSetAttribute(critic_kernel, cudaFuncAttributeMaxDynamicSharedMemorySize, SMEM_BYTES);

    prep_weights<<<48, 256>>>(Wk, Wq, Wv, W1);
    critic_kernel<<<512, 256, SMEM_BYTES>>>(states, policies, actions,
                                            bk, bq, bv, W2, out, out_size);
}

// round 5
// speedup vs baseline: 1.1082x; 1.0769x over previous
#include <cuda_runtime.h>

// ---------------------------------------------------------------------------
// ScalarDotProductCriticNetworkV8 — fused kernel, 2 batches per CTA (R5).
//
// Shapes: B=512, N=16, A=16, OBS=112, D=128, H=64, F_IN=128. Grid=256, NB=2.
//
// R5 = R4 + fix: weight-output row index was wt[(bl*16+(t&15))*17+...],
// must be wt[(bl*16+(t>>4))*17+(t&15)]  (row = j = t>>4).
//
// R4 vs R3 (71.7us): each CTA processes 2 batches so every weight LDG feeds
// 16 FFMA2 (vs 8) -> weight traffic halved, inner loops FMA-pipe-bound.
// unroll 4 restores MLP~4 on the L2-resident weight stream.
// occ 2 (smem 90.8KB), 256 CTAs <= 296 capacity -> single wave.
// ---------------------------------------------------------------------------

#define ULL unsigned long long

#define PACK2(d, lo, hi) asm("mov.b64 %0, {%1, %2};" : "=l"(d) : "f"(lo), "f"(hi))
#define UNPACK2(lo, hi, v) asm("mov.b64 {%0, %1}, %2;" : "=f"(lo), "=f"(hi) : "l"(v))
#define FMA2(acc, a, b) asm("fma.rn.f32x2 %0, %1, %2, %0;" : "+l"(acc) : "l"(a), "l"(b))
#define TANHA(y, x) asm("tanh.approx.f32 %0, %1;" : "=f"(y) : "f"(x))

// Pre-transposed weights (scratch; filled by prep kernel each launch).
__device__ float g_WkT[112 * 128];   // [kk][c]
__device__ float g_WqT[112 * 128];   // [kk][c]
__device__ float g_WvT[128 * 128];   // [f][c]
__device__ float g_W1T[128 * 64];    // [d][h]

__global__ void prep_weights(const float* __restrict__ Wk, const float* __restrict__ Wq,
                             const float* __restrict__ Wv, const float* __restrict__ W1) {
    int t = blockIdx.x * blockDim.x + threadIdx.x;
    int stride = gridDim.x * blockDim.x;
    for (int i = t; i < 112 * 128; i += stride) {
        int kk = i >> 7, c = i & 127;
        g_WkT[i] = Wk[c * 112 + kk];
        g_WqT[i] = Wq[c * 112 + kk];
    }
    for (int i = t; i < 128 * 128; i += stride) {
        int f = i >> 7, c = i & 127;
        g_WvT[i] = Wv[c * 128 + f];
    }
    for (int i = t; i < 128 * 64; i += stride) {
        int d = i >> 6, h = i & 63;
        g_W1T[i] = W1[h * 128 + d];
    }
}

// Shared memory layout (floats). 32 rows = 2 batches x 16; transposed arrays
// use row-stride 36 (144B, 16B-aligned for LDS.128).
//  stT   [112][36] @0
//  actT  [16][36]  @4032
//  polT  [16][36]  @4608
//  X @5184 (aliased):
//    phases 1-3: k_s[32][128] @5184, q_s[32][129] @9280   (ends 13408)
//    phases 4-5: aw1[32][65] @5184, adw1[32][65] @7264, sw1[32][64] @9344
//  avoT  [128][36] @13408
//  avdT  [128][36] @18016
//  wt    [32][17]  @22624   (row = bl*16 + j)
//  w2s   [64]      @23168
#define OFF_STT   0
#define OFF_ACTT  4032
#define OFF_POLT  4608
#define OFF_K     5184
#define OFF_Q     9280
#define OFF_AW1   5184
#define OFF_ADW1  7264
#define OFF_SW1   9344
#define OFF_AVO   13408
#define OFF_AVD   18016
#define OFF_WT    22624
#define OFF_W2    23168
#define SMEM_FLOATS 23232
#define SMEM_BYTES  (SMEM_FLOATS * 4)

__global__ void __launch_bounds__(256, 2)
critic_kernel(const float* __restrict__ states,
              const float* __restrict__ policies,
              const float* __restrict__ actions,
              const float* __restrict__ bk,
              const float* __restrict__ bq,
              const float* __restrict__ bv,
              const float* __restrict__ W2,
              float* __restrict__ out,
              int out_size) {
    extern __shared__ float sm[];
    float* stT  = sm + OFF_STT;
    float* actT = sm + OFF_ACTT;
    float* polT = sm + OFF_POLT;
    float* k_s  = sm + OFF_K;
    float* q_s  = sm + OFF_Q;
    float* aw1  = sm + OFF_AW1;
    float* adw1 = sm + OFF_ADW1;
    float* sw1  = sm + OFF_SW1;
    float* avoT = sm + OFF_AVO;
    float* avdT = sm + OFF_AVD;
    float* wt   = sm + OFF_WT;
    float* w2s  = sm + OFF_W2;

    const int t = threadIdx.x;
    const int b0 = blockIdx.x * 2;

    // ---- load inputs (transposed into smem; rows packed bl*16+r) ----
    {
        const float* stb = states + b0 * (16 * 112);
        for (int idx = t; idx < 32 * 112; idx += 256) {
            int rg = idx / 112, kk = idx - rg * 112;
            stT[kk * 36 + rg] = stb[idx];
        }
#pragma unroll
        for (int s = 0; s < 2; s++) {
            int idx = t + 256 * s;
            int bl = idx >> 8, rem = idx & 255, i = rem >> 4, a = rem & 15;
            actT[a * 36 + bl * 16 + i] = actions[b0 * 256 + idx];
            polT[a * 36 + bl * 16 + i] = policies[b0 * 256 + idx];
        }
        if (t < 64) w2s[t] = W2[t];
    }
    __syncthreads();

    // ---- phase 1: k = st@Wk.T + bk ; q = (st@Wq.T + bq)/sqrt(D), 32 rows ----
    {
        const int which = t >> 7, c = t & 127;
        const float* WT = which ? g_WqT : g_WkT;
        const float bias = which ? bq[c] : bk[c];
        ULL acc[16];
#pragma unroll
        for (int rp = 0; rp < 16; rp++) PACK2(acc[rp], bias, bias);
#pragma unroll 4
        for (int kk = 0; kk < 112; kk++) {
            float w = WT[kk * 128 + c];
            ULL w2; PACK2(w2, w, w);
            const ulonglong2* sp = reinterpret_cast<const ulonglong2*>(stT + kk * 36);
#pragma unroll
            for (int q4 = 0; q4 < 8; q4++) {
                ulonglong2 sv = sp[q4];
                FMA2(acc[2 * q4], w2, sv.x);
                FMA2(acc[2 * q4 + 1], w2, sv.y);
            }
        }
        if (which == 0) {
#pragma unroll
            for (int rp = 0; rp < 16; rp++) {
                float lo, hi; UNPACK2(lo, hi, acc[rp]);
                k_s[(2 * rp) * 128 + c] = lo;
                k_s[(2 * rp + 1) * 128 + c] = hi;
            }
        } else {
            const float s = 0.08838834764831845f;  // 1/sqrt(128)
#pragma unroll
            for (int rp = 0; rp < 16; rp++) {
                float lo, hi; UNPACK2(lo, hi, acc[rp]);
                q_s[(2 * rp) * 129 + c] = lo * s;
                q_s[(2 * rp + 1) * 129 + c] = hi * s;
            }
        }
    }
    __syncthreads();

    // ---- phase 2: avoff = tanh([st;act]@Wv.T+bv), avdiag = tanh([st;pol]@Wv.T+bv) ----
    {
        const int which = t >> 7, c = t & 127;
        const float bias = bv[c];
        ULL acc[16];
#pragma unroll
        for (int rp = 0; rp < 16; rp++) PACK2(acc[rp], bias, bias);
#pragma unroll 4
        for (int f = 0; f < 112; f++) {
            float w = g_WvT[f * 128 + c];
            ULL w2; PACK2(w2, w, w);
            const ulonglong2* sp = reinterpret_cast<const ulonglong2*>(stT + f * 36);
#pragma unroll
            for (int q4 = 0; q4 < 8; q4++) {
                ulonglong2 sv = sp[q4];
                FMA2(acc[2 * q4], w2, sv.x);
                FMA2(acc[2 * q4 + 1], w2, sv.y);
            }
        }
        const float* tailT = which ? polT : actT;
#pragma unroll 4
        for (int f = 0; f < 16; f++) {
            float w = g_WvT[(112 + f) * 128 + c];
            ULL w2; PACK2(w2, w, w);
            const ulonglong2* sp = reinterpret_cast<const ulonglong2*>(tailT + f * 36);
#pragma unroll
            for (int q4 = 0; q4 < 8; q4++) {
                ulonglong2 sv = sp[q4];
                FMA2(acc[2 * q4], w2, sv.x);
                FMA2(acc[2 * q4 + 1], w2, sv.y);
            }
        }
        float v[32];
#pragma unroll
        for (int rp = 0; rp < 16; rp++) {
            float lo, hi; UNPACK2(lo, hi, acc[rp]);
            TANHA(v[2 * rp], lo);
            TANHA(v[2 * rp + 1], hi);
        }
        float* dst = (which ? avdT : avoT) + c * 36;
#pragma unroll
        for (int q4 = 0; q4 < 8; q4++)
            *reinterpret_cast<float4*>(dst + 4 * q4) =
                make_float4(v[4 * q4], v[4 * q4 + 1], v[4 * q4 + 2], v[4 * q4 + 3]);
    }
    __syncthreads();

    // ---- phase 3: scores + softmax over i (shfl within 16-lane groups) ----
#pragma unroll
    for (int s = 0; s < 2; s++) {
        int id = t + 256 * s;
        int bl = id >> 8, j = (id >> 4) & 15, i = id & 15;
        const float* qp = q_s + (bl * 16 + i) * 129;
        const float* kp = k_s + (bl * 16 + j) * 128;
        float s0 = 0.f, s1 = 0.f, s2 = 0.f, s3 = 0.f;
#pragma unroll 8
        for (int d = 0; d < 128; d += 4) {
            s0 = fmaf(qp[d + 0], kp[d + 0], s0);
            s1 = fmaf(qp[d + 1], kp[d + 1], s1);
            s2 = fmaf(qp[d + 2], kp[d + 2], s2);
            s3 = fmaf(qp[d + 3], kp[d + 3], s3);
        }
        float sc = (s0 + s1) + (s2 + s3);
        float m = sc;
#pragma unroll
        for (int o = 8; o; o >>= 1) m = fmaxf(m, __shfl_xor_sync(0xffffffffu, m, o));
        float e = __expf(sc - m);
        float sum = e;
#pragma unroll
        for (int o = 8; o; o >>= 1) sum += __shfl_xor_sync(0xffffffffu, sum, o);
        wt[(bl * 16 + j) * 17 + i] = e / sum;
    }
    __syncthreads();

    // ---- phase 4: AW1 = avoff@W1.T, AdW1 = avdiag@W1.T  ([32][64] each) ----
    {
        int h = t & 63, g = t >> 6;
        int m = g & 1, r0 = (g >> 1) * 16;
        const float* srcT = m ? avdT : avoT;
        float* dst = m ? adw1 : aw1;
        ULL acc[8] = {};
#pragma unroll 4
        for (int d = 0; d < 128; d++) {
            float w = g_W1T[d * 64 + h];
            ULL w2; PACK2(w2, w, w);
            const ulonglong2* sp = reinterpret_cast<const ulonglong2*>(srcT + d * 36 + r0);
#pragma unroll
            for (int q4 = 0; q4 < 4; q4++) {
                ulonglong2 sv = sp[q4];
                FMA2(acc[2 * q4], w2, sv.x);
                FMA2(acc[2 * q4 + 1], w2, sv.y);
            }
        }
#pragma unroll
        for (int rp = 0; rp < 8; rp++) {
            float lo, hi; UNPACK2(lo, hi, acc[rp]);
            dst[(r0 + 2 * rp) * 65 + h] = lo;
            dst[(r0 + 2 * rp + 1) * 65 + h] = hi;
        }
    }
    __syncthreads();

    // ---- phase 5a: SW1[ag,h] = sum_i wt[ag,i] * AW1[bl*16+i,h] ----
    {
        int h = t & 63, g = t >> 6, a0 = g * 8;
        int blr = (a0 >> 4) * 16;  // row base of this group's batch
        float acc[8] = {};
#pragma unroll
        for (int i = 0; i < 16; i++) {
            float aw_ = aw1[(blr + i) * 65 + h];
#pragma unroll
            for (int aa = 0; aa < 8; aa++)
                acc[aa] = fmaf(wt[(a0 + aa) * 17 + i], aw_, acc[aa]);
        }
#pragma unroll
        for (int aa = 0; aa < 8; aa++) sw1[(a0 + aa) * 64 + h] = acc[aa];
    }
    __syncthreads();

    // ---- phase 5b: value + weight outputs ----
    {
        int a = t >> 4, j = t & 15;
#pragma unroll
        for (int bl = 0; bl < 2; bl++) {
            int ag = bl * 16 + a, jg = bl * 16 + j;
            float waj = wt[ag * 17 + j];
            float acc = 0.f;
#pragma unroll 8
            for (int h = 0; h < 64; h++) {
                float dd = adw1[jg * 65 + h] - aw1[jg * 65 + h];
                float nf = (sw1[ag * 64 + h] + dd * waj) * 0.0625f;
                float v = nf > 0.f ? nf : 0.01f * nf;
                acc = fmaf(v, w2s[h], acc);
            }
            out[(b0 + bl) * 256 + t] = acc;                   // value[b, a, j, 0]
            if (out_size >= 262144)                            // weight[b, j, i]: row = t>>4
                out[131072 + (b0 + bl) * 256 + t] = wt[(bl * 16 + (t >> 4)) * 17 + (t & 15)];
        }
    }
}

extern "C" void kernel_launch(void* const* d_in, const int* in_sizes, int n_in,
                              void* d_out, int out_size) {
    const float* states   = (const float*)d_in[0];
    const float* policies = (const float*)d_in[1];
    const float* actions  = (const float*)d_in[2];
    const float* Wk       = (const float*)d_in[3];
    const float* bk       = (const float*)d_in[4];
    const float* Wq       = (const float*)d_in[5];
    const float* bq       = (const float*)d_in[6];
    const float* Wv       = (const float*)d_in[7];
    const float* bv       = (const float*)d_in[8];
    const float* W1       = (const float*)d_in[9];
    const float* W2       = (const float*)d_in[10];
    float* out = (float*)d_out;

    cudaFuncSetAttribute(critic_kernel, cudaFuncAttributeMaxDynamicSharedMemorySize, SMEM_BYTES);

    prep_weights<<<48, 256>>>(Wk, Wq, Wv, W1);
    critic_kernel<<<256, 256, SMEM_BYTES>>>(states, policies, actions,
                                            bk, bq, bv, W2, out, out_size);
}

// round 6
// speedup vs baseline: 1.4343x; 1.2943x over previous
#include <cuda_runtime.h>

// ---------------------------------------------------------------------------
// ScalarDotProductCriticNetworkV8 — fused kernel, 2 batches per CTA (R6).
//
// Shapes: B=512, N=16, A=16, OBS=112, D=128, H=64, F_IN=128. Grid=256, NB=2.
//
// R6 vs R5 (66.6us, L1TEX 69% = bottleneck): halve LDS.128 traffic.
//  * P1: thread computes BOTH k and q (same activation loads feed 2x FMA)
//  * P2: states partial sum computed ONCE, shared by avoff/avdiag tails
//  * P4: 2 h-columns per thread (same activation loads feed 2x FMA)
//  * phase order P1 -> P3 -> P2 so avoT/avdT alias dead k/q; aw1/adw1 alias
//    dead stT. smem 90.8KB -> 66.6KB.
// Per-thread LDS.128: 2432 -> 1280; FFMA2: 4864 -> 3968.
// ---------------------------------------------------------------------------

#define ULL unsigned long long

#define PACK2(d, lo, hi) asm("mov.b64 %0, {%1, %2};" : "=l"(d) : "f"(lo), "f"(hi))
#define UNPACK2(lo, hi, v) asm("mov.b64 {%0, %1}, %2;" : "=f"(lo), "=f"(hi) : "l"(v))
#define FMA2(acc, a, b) asm("fma.rn.f32x2 %0, %1, %2, %0;" : "+l"(acc) : "l"(a), "l"(b))
#define TANHA(y, x) asm("tanh.approx.f32 %0, %1;" : "=f"(y) : "f"(x))

// Pre-transposed weights (scratch; filled by prep kernel each launch).
__device__ float g_WkT[112 * 128];   // [kk][c]
__device__ float g_WqT[112 * 128];   // [kk][c]
__device__ float g_WvT[128 * 128];   // [f][c]
__device__ float g_W1T[128 * 64];    // [d][h]

__global__ void prep_weights(const float* __restrict__ Wk, const float* __restrict__ Wq,
                             const float* __restrict__ Wv, const float* __restrict__ W1) {
    int t = blockIdx.x * blockDim.x + threadIdx.x;
    int stride = gridDim.x * blockDim.x;
    for (int i = t; i < 112 * 128; i += stride) {
        int kk = i >> 7, c = i & 127;
        g_WkT[i] = Wk[c * 112 + kk];
        g_WqT[i] = Wq[c * 112 + kk];
    }
    for (int i = t; i < 128 * 128; i += stride) {
        int f = i >> 7, c = i & 127;
        g_WvT[i] = Wv[c * 128 + f];
    }
    for (int i = t; i < 128 * 64; i += stride) {
        int d = i >> 6, h = i & 63;
        g_W1T[i] = W1[h * 128 + d];
    }
}

// Shared memory (floats), two aliased regions:
//  A @0 (5184):   phases 0-2: stT[112][36]@0, actT[16][36]@4032, polT[16][36]@4608
//                 phases 4-5: aw1[32][65]@0, adw1[32][65]@2080
//  B @5184 (9216): phases 1,3: k_s[32][128]@5184, q_s[32][129]@9280
//                  phases 2,4: avoT[128][36]@5184, avdT[128][36]@9792
//  sw1[32][64]@14400, wt[32][17]@16448, w2s[64]@16992
#define OFF_STT   0
#define OFF_ACTT  4032
#define OFF_POLT  4608
#define OFF_AW1   0
#define OFF_ADW1  2080
#define OFF_K     5184
#define OFF_Q     9280
#define OFF_AVO   5184
#define OFF_AVD   9792
#define OFF_SW1   14400
#define OFF_WT    16448
#define OFF_W2    16992
#define SMEM_FLOATS 17056
#define SMEM_BYTES  (SMEM_FLOATS * 4)

__global__ void __launch_bounds__(256, 2)
critic_kernel(const float* __restrict__ states,
              const float* __restrict__ policies,
              const float* __restrict__ actions,
              const float* __restrict__ bk,
              const float* __restrict__ bq,
              const float* __restrict__ bv,
              const float* __restrict__ W2,
              float* __restrict__ out,
              int out_size) {
    extern __shared__ float sm[];
    float* stT  = sm + OFF_STT;
    float* actT = sm + OFF_ACTT;
    float* polT = sm + OFF_POLT;
    float* aw1  = sm + OFF_AW1;
    float* adw1 = sm + OFF_ADW1;
    float* k_s  = sm + OFF_K;
    float* q_s  = sm + OFF_Q;
    float* avoT = sm + OFF_AVO;
    float* avdT = sm + OFF_AVD;
    float* sw1  = sm + OFF_SW1;
    float* wt   = sm + OFF_WT;
    float* w2s  = sm + OFF_W2;

    const int t = threadIdx.x;
    const int b0 = blockIdx.x * 2;

    // ---- phase 0: load inputs (transposed; rows packed bl*16+r) ----
    {
        const float* stb = states + b0 * (16 * 112);
        for (int idx = t; idx < 32 * 112; idx += 256) {
            int rg = idx / 112, kk = idx - rg * 112;
            stT[kk * 36 + rg] = stb[idx];
        }
#pragma unroll
        for (int s = 0; s < 2; s++) {
            int idx = t + 256 * s;
            int bl = idx >> 8, rem = idx & 255, i = rem >> 4, a = rem & 15;
            actT[a * 36 + bl * 16 + i] = actions[b0 * 256 + idx];
            polT[a * 36 + bl * 16 + i] = policies[b0 * 256 + idx];
        }
        if (t < 64) w2s[t] = W2[t];
    }
    __syncthreads();

    // ---- phase 1: k AND q for 16 rows per thread (c = col, bl = batch) ----
    {
        const int c = t & 127, bl = t >> 7;
        const int rbase = bl * 16;
        ULL ka[8], qa[8];
        {
            float bkc = bk[c], bqc = bq[c];
#pragma unroll
            for (int rp = 0; rp < 8; rp++) { PACK2(ka[rp], bkc, bkc); PACK2(qa[rp], bqc, bqc); }
        }
#pragma unroll 4
        for (int kk = 0; kk < 112; kk++) {
            float wk = g_WkT[kk * 128 + c];
            float wq = g_WqT[kk * 128 + c];
            ULL wk2, wq2; PACK2(wk2, wk, wk); PACK2(wq2, wq, wq);
            const ulonglong2* sp = reinterpret_cast<const ulonglong2*>(stT + kk * 36 + rbase);
#pragma unroll
            for (int p4 = 0; p4 < 4; p4++) {
                ulonglong2 sv = sp[p4];
                FMA2(ka[2 * p4], wk2, sv.x); FMA2(ka[2 * p4 + 1], wk2, sv.y);
                FMA2(qa[2 * p4], wq2, sv.x); FMA2(qa[2 * p4 + 1], wq2, sv.y);
            }
        }
        const float s = 0.08838834764831845f;  // 1/sqrt(128)
#pragma unroll
        for (int rp = 0; rp < 8; rp++) {
            float lo, hi;
            UNPACK2(lo, hi, ka[rp]);
            k_s[(rbase + 2 * rp) * 128 + c] = lo;
            k_s[(rbase + 2 * rp + 1) * 128 + c] = hi;
            UNPACK2(lo, hi, qa[rp]);
            q_s[(rbase + 2 * rp) * 129 + c] = lo * s;
            q_s[(rbase + 2 * rp + 1) * 129 + c] = hi * s;
        }
    }
    __syncthreads();

    // ---- phase 3 (moved early): scores + softmax over i ----
#pragma unroll
    for (int s = 0; s < 2; s++) {
        int id = t + 256 * s;
        int bl = id >> 8, j = (id >> 4) & 15, i = id & 15;
        const float* qp = q_s + (bl * 16 + i) * 129;
        const float* kp = k_s + (bl * 16 + j) * 128;
        float s0 = 0.f, s1 = 0.f, s2 = 0.f, s3 = 0.f;
#pragma unroll 8
        for (int d = 0; d < 128; d += 4) {
            s0 = fmaf(qp[d + 0], kp[d + 0], s0);
            s1 = fmaf(qp[d + 1], kp[d + 1], s1);
            s2 = fmaf(qp[d + 2], kp[d + 2], s2);
            s3 = fmaf(qp[d + 3], kp[d + 3], s3);
        }
        float sc = (s0 + s1) + (s2 + s3);
        float m = sc;
#pragma unroll
        for (int o = 8; o; o >>= 1) m = fmaxf(m, __shfl_xor_sync(0xffffffffu, m, o));
        float e = __expf(sc - m);
        float sum = e;
#pragma unroll
        for (int o = 8; o; o >>= 1) sum += __shfl_xor_sync(0xffffffffu, sum, o);
        wt[(bl * 16 + j) * 17 + i] = e / sum;
    }
    __syncthreads();

    // ---- phase 2: avoff/avdiag with shared states partial (16 rows/thread) ----
    // (avoT/avdT overwrite k_s/q_s: phase 3 is already done)
    {
        const int c = t & 127, bl = t >> 7;
        const int rbase = bl * 16;
        ULL sh[8];
        {
            float bvc = bv[c];
#pragma unroll
            for (int rp = 0; rp < 8; rp++) PACK2(sh[rp], bvc, bvc);
        }
#pragma unroll 4
        for (int f = 0; f < 112; f++) {
            float w = g_WvT[f * 128 + c];
            ULL w2; PACK2(w2, w, w);
            const ulonglong2* sp = reinterpret_cast<const ulonglong2*>(stT + f * 36 + rbase);
#pragma unroll
            for (int p4 = 0; p4 < 4; p4++) {
                ulonglong2 sv = sp[p4];
                FMA2(sh[2 * p4], w2, sv.x); FMA2(sh[2 * p4 + 1], w2, sv.y);
            }
        }
        // actions tail -> avoff
        {
            ULL wk_[8];
#pragma unroll
            for (int rp = 0; rp < 8; rp++) wk_[rp] = sh[rp];
#pragma unroll 4
            for (int f = 0; f < 16; f++) {
                float w = g_WvT[(112 + f) * 128 + c];
                ULL w2; PACK2(w2, w, w);
                const ulonglong2* sp = reinterpret_cast<const ulonglong2*>(actT + f * 36 + rbase);
#pragma unroll
                for (int p4 = 0; p4 < 4; p4++) {
                    ulonglong2 sv = sp[p4];
                    FMA2(wk_[2 * p4], w2, sv.x); FMA2(wk_[2 * p4 + 1], w2, sv.y);
                }
            }
            float v[16];
#pragma unroll
            for (int rp = 0; rp < 8; rp++) {
                float lo, hi; UNPACK2(lo, hi, wk_[rp]);
                TANHA(v[2 * rp], lo); TANHA(v[2 * rp + 1], hi);
            }
            float* dst = avoT + c * 36 + rbase;
#pragma unroll
            for (int p4 = 0; p4 < 4; p4++)
                *reinterpret_cast<float4*>(dst + 4 * p4) =
                    make_float4(v[4 * p4], v[4 * p4 + 1], v[4 * p4 + 2], v[4 * p4 + 3]);
        }
        // policies tail -> avdiag
        {
            ULL wk_[8];
#pragma unroll
            for (int rp = 0; rp < 8; rp++) wk_[rp] = sh[rp];
#pragma unroll 4
            for (int f = 0; f < 16; f++) {
                float w = g_WvT[(112 + f) * 128 + c];
                ULL w2; PACK2(w2, w, w);
                const ulonglong2* sp = reinterpret_cast<const ulonglong2*>(polT + f * 36 + rbase);
#pragma unroll
                for (int p4 = 0; p4 < 4; p4++) {
                    ulonglong2 sv = sp[p4];
                    FMA2(wk_[2 * p4], w2, sv.x); FMA2(wk_[2 * p4 + 1], w2, sv.y);
                }
            }
            float v[16];
#pragma unroll
            for (int rp = 0; rp < 8; rp++) {
                float lo, hi; UNPACK2(lo, hi, wk_[rp]);
                TANHA(v[2 * rp], lo); TANHA(v[2 * rp + 1], hi);
            }
            float* dst = avdT + c * 36 + rbase;
#pragma unroll
            for (int p4 = 0; p4 < 4; p4++)
                *reinterpret_cast<float4*>(dst + 4 * p4) =
                    make_float4(v[4 * p4], v[4 * p4 + 1], v[4 * p4 + 2], v[4 * p4 + 3]);
        }
    }
    __syncthreads();

    // ---- phase 4: AW1/AdW1, 2 h-columns x 8 rows per thread ----
    // (aw1/adw1 overwrite stT/actT/polT: phase 2 is done)
    {
        const int h = t & 31, m = (t >> 5) & 1, qd = t >> 6;  // qd in 0..3
        const int r0 = qd * 8;
        const float* srcT = m ? avdT : avoT;
        float* dst = m ? adw1 : aw1;
        ULL a0[4] = {}, a1[4] = {};
#pragma unroll 4
        for (int d = 0; d < 128; d++) {
            float w0 = g_W1T[d * 64 + h];
            float w1 = g_W1T[d * 64 + h + 32];
            ULL w02, w12; PACK2(w02, w0, w0); PACK2(w12, w1, w1);
            const ulonglong2* sp = reinterpret_cast<const ulonglong2*>(srcT + d * 36 + r0);
            ulonglong2 sv0 = sp[0], sv1 = sp[1];
            FMA2(a0[0], w02, sv0.x); FMA2(a0[1], w02, sv0.y);
            FMA2(a0[2], w02, sv1.x); FMA2(a0[3], w02, sv1.y);
            FMA2(a1[0], w12, sv0.x); FMA2(a1[1], w12, sv0.y);
            FMA2(a1[2], w12, sv1.x); FMA2(a1[3], w12, sv1.y);
        }
#pragma unroll
        for (int rp = 0; rp < 4; rp++) {
            float lo, hi;
            UNPACK2(lo, hi, a0[rp]);
            dst[(r0 + 2 * rp) * 65 + h] = lo;
            dst[(r0 + 2 * rp + 1) * 65 + h] = hi;
            UNPACK2(lo, hi, a1[rp]);
            dst[(r0 + 2 * rp) * 65 + h + 32] = lo;
            dst[(r0 + 2 * rp + 1) * 65 + h + 32] = hi;
        }
    }
    __syncthreads();

    // ---- phase 5a: SW1[ag,h] = sum_i wt[ag,i] * AW1[bl*16+i,h] ----
    {
        int h = t & 63, g = t >> 6, a0 = g * 8;
        int blr = (a0 >> 4) * 16;
        float acc[8] = {};
#pragma unroll
        for (int i = 0; i < 16; i++) {
            float aw_ = aw1[(blr + i) * 65 + h];
#pragma unroll
            for (int aa = 0; aa < 8; aa++)
                acc[aa] = fmaf(wt[(a0 + aa) * 17 + i], aw_, acc[aa]);
        }
#pragma unroll
        for (int aa = 0; aa < 8; aa++) sw1[(a0 + aa) * 64 + h] = acc[aa];
    }
    __syncthreads();

    // ---- phase 5b: value + weight outputs ----
    {
        int a = t >> 4, j = t & 15;
#pragma unroll
        for (int bl = 0; bl < 2; bl++) {
            int ag = bl * 16 + a, jg = bl * 16 + j;
            float waj = wt[ag * 17 + j];
            float acc = 0.f;
#pragma unroll 8
            for (int h = 0; h < 64; h++) {
                float dd = adw1[jg * 65 + h] - aw1[jg * 65 + h];
                float nf = (sw1[ag * 64 + h] + dd * waj) * 0.0625f;
                float v = nf > 0.f ? nf : 0.01f * nf;
                acc = fmaf(v, w2s[h], acc);
            }
            out[(b0 + bl) * 256 + t] = acc;                   // value[b, a, j, 0]
            if (out_size >= 262144)                            // weight[b, j, i]
                out[131072 + (b0 + bl) * 256 + t] = wt[(bl * 16 + (t >> 4)) * 17 + (t & 15)];
        }
    }
}

extern "C" void kernel_launch(void* const* d_in, const int* in_sizes, int n_in,
                              void* d_out, int out_size) {
    const float* states   = (const float*)d_in[0];
    const float* policies = (const float*)d_in[1];
    const float* actions  = (const float*)d_in[2];
    const float* Wk       = (const float*)d_in[3];
    const float* bk       = (const float*)d_in[4];
    const float* Wq       = (const float*)d_in[5];
    const float* bq       = (const float*)d_in[6];
    const float* Wv       = (const float*)d_in[7];
    const float* bv       = (const float*)d_in[8];
    const float* W1       = (const float*)d_in[9];
    const float* W2       = (const float*)d_in[10];
    float* out = (float*)d_out;

    cudaFuncSetAttribute(critic_kernel, cudaFuncAttributeMaxDynamicSharedMemorySize, SMEM_BYTES);

    prep_weights<<<48, 256>>>(Wk, Wq, Wv, W1);
    critic_kernel<<<256, 256, SMEM_BYTES>>>(states, policies, actions,
                                            bk, bq, bv, W2, out, out_size);
}